// round 3
// baseline (speedup 1.0000x reference)
#include <cuda_runtime.h>
#include <math.h>

#define N_AA_C   300000
#define N_PROT_C 30000
#define D        128
#define DOUT     64
#define E_AP_MAX 300000
#define E_PP_MAX 960000
#define BATCH    16384
#define NEG      0.2f

// ---------------- device scratch (static; no runtime allocation) -------------
__device__ float g_xl_pp[N_PROT_C * D];   // 15.4 MB (L2-resident)
__device__ float g_xr_pp[BATCH * D];
__device__ float g_xr_ap[BATCH * D];
__device__ float g_hid[BATCH * D];
__device__ float g_accap[BATCH * D];      // AP aggregated x (input space)
__device__ float g_ppout[BATCH * D];      // PP branch output
__device__ float g_logits[E_AP_MAX];

__device__ int g_cnt_ap[BATCH];
__device__ int g_cnt_pp[BATCH];
__device__ int g_off_ap[BATCH + 1];
__device__ int g_off_pp[BATCH + 1];
__device__ int g_cur_ap[BATCH];
__device__ int g_cur_pp[BATCH];
__device__ int g_src_ap[E_AP_MAX];
__device__ int g_dst_ap[E_AP_MAX];
__device__ int g_src_pp[E_PP_MAX];

__device__ __forceinline__ float lrelu(float x) { return x > 0.f ? x : NEG * x; }

// packed f32x2 helpers (Blackwell FFMA2 — only reachable via PTX)
__device__ __forceinline__ unsigned long long splat2(float x) {
    unsigned long long d;
    asm("mov.b64 %0, {%1, %1};" : "=l"(d) : "r"(__float_as_uint(x)));
    return d;
}
__device__ __forceinline__ unsigned long long pack2(float lo, float hi) {
    unsigned long long d;
    asm("mov.b64 %0, {%1, %2};" : "=l"(d) : "r"(__float_as_uint(lo)), "r"(__float_as_uint(hi)));
    return d;
}
__device__ __forceinline__ float2 unpack2(unsigned long long u) {
    float2 f;
    asm("mov.b64 {%0, %1}, %2;" : "=f"(f.x), "=f"(f.y) : "l"(u));
    return f;
}
__device__ __forceinline__ unsigned long long ffma2(
    unsigned long long a, unsigned long long b, unsigned long long c) {
    unsigned long long d;
    asm("fma.rn.f32x2 %0, %1, %2, %3;" : "=l"(d) : "l"(a), "l"(b), "l"(c));
    return d;
}

// ---------------- fused preprocessing kernels --------------------------------
__global__ void zero2_kernel(int* a, int* b) {
    int i = blockIdx.x * blockDim.x + threadIdx.x;
    if (i < BATCH) a[i] = 0;
    else if (i < 2 * BATCH) b[i - BATCH] = 0;
}

__global__ void hist2_kernel(const int* __restrict__ ei_ap, int E_ap, int* __restrict__ cnt_ap,
                             const int* __restrict__ ei_pp, int E_pp, int* __restrict__ cnt_pp) {
    int i = blockIdx.x * blockDim.x + threadIdx.x;
    if (i < E_ap) {
        int d = ei_ap[E_ap + i];
        if (d < BATCH) atomicAdd(&cnt_ap[d], 1);
    } else if (i < E_ap + E_pp) {
        int j = i - E_ap;
        int d = ei_pp[E_pp + j];
        if (d < BATCH) atomicAdd(&cnt_pp[d], 1);
    }
}

__global__ void scan2_kernel(const int* __restrict__ cnt_ap, int* __restrict__ off_ap, int* __restrict__ cur_ap,
                             const int* __restrict__ cnt_pp, int* __restrict__ off_pp, int* __restrict__ cur_pp) {
    const int* cnt = blockIdx.x ? cnt_pp : cnt_ap;
    int* off = blockIdx.x ? off_pp : off_ap;
    int* cur = blockIdx.x ? cur_pp : cur_ap;
    __shared__ int s[1024];
    int t = threadIdx.x;
    int v[16];
    int run = 0;
#pragma unroll
    for (int i = 0; i < 16; i++) { v[i] = run; run += cnt[t * 16 + i]; }
    s[t] = run;
    __syncthreads();
    for (int d = 1; d < 1024; d <<= 1) {
        int add = (t >= d) ? s[t - d] : 0;
        __syncthreads();
        s[t] += add;
        __syncthreads();
    }
    int base = (t > 0) ? s[t - 1] : 0;
#pragma unroll
    for (int i = 0; i < 16; i++) {
        int o = base + v[i];
        off[t * 16 + i] = o;
        cur[t * 16 + i] = o;
    }
    if (t == 1023) off[16384] = s[1023];
}

__global__ void scatter2_kernel(const int* __restrict__ ei_ap, int E_ap, int* __restrict__ cur_ap,
                                int* __restrict__ src_ap, int* __restrict__ dst_ap,
                                const int* __restrict__ ei_pp, int E_pp, int* __restrict__ cur_pp,
                                int* __restrict__ src_pp) {
    int i = blockIdx.x * blockDim.x + threadIdx.x;
    if (i < E_ap) {
        int d = ei_ap[E_ap + i];
        if (d < BATCH) {
            int p = atomicAdd(&cur_ap[d], 1);
            src_ap[p] = ei_ap[i];
            dst_ap[p] = d;
        }
    } else if (i < E_ap + E_pp) {
        int j = i - E_ap;
        int d = ei_pp[E_pp + j];
        if (d < BATCH) {
            int p = atomicAdd(&cur_pp[d], 1);
            src_pp[p] = ei_pp[j];
        }
    }
}

// ---------------- 128x128-tile GEMM, 8x8 per-thread register block -----------
// MODE 0: Y = X @ W + bias1                       (plain rows)
// MODE 1: gather rows via srcs; compute per-row logits only (GATv2 epilogue)
// MODE 2: Y = X @ W + bias1 + bias2 + addmat      (post-aggregation GEMM)
template <int MODE>
__global__ void __launch_bounds__(256) gemm_kernel(
    const float* __restrict__ X, const float* __restrict__ W,
    const float* __restrict__ bias1, const float* __restrict__ bias2,
    float* __restrict__ Y, int nrows_const,
    const int* __restrict__ srcs, const int* __restrict__ total_ptr,
    const int* __restrict__ dst_arr, const float* __restrict__ xr,
    const float* __restrict__ att, float* __restrict__ logits,
    const float* __restrict__ addmat) {
    int total = (MODE == 1) ? *total_ptr : nrows_const;
    int row0 = blockIdx.x * 128;
    if (row0 >= total) return;

    extern __shared__ float sm[];
    float* Ws = sm;               // [k*128 + n], 64KB
    float* Xs = sm + D * D;       // [k*128 + m] (transposed), 64KB
    int t = threadIdx.x;
    int tx = t & 15, ty = t >> 4;        // 16x16 thread grid
    int tx8 = tx * 8, ty8 = ty * 8;

    // W is [k][n] row-major -> already k-major
    for (int i = t; i < 4096; i += 256) ((float4*)Ws)[i] = ((const float4*)W)[i];
    // X tile transposed into Xs[k*128 + m]
    for (int i = t; i < 4096; i += 256) {
        int m = i & 127, k4 = i >> 7;
        int r = row0 + m;
        int rr = 0;
        if (r < total) rr = (MODE == 1) ? srcs[r] : r;
        float4 v = ((const float4*)X)[(size_t)rr * 32 + k4];
        Xs[(4 * k4 + 0) * 128 + m] = v.x;
        Xs[(4 * k4 + 1) * 128 + m] = v.y;
        Xs[(4 * k4 + 2) * 128 + m] = v.z;
        Xs[(4 * k4 + 3) * 128 + m] = v.w;
    }
    __syncthreads();

    // accumulator init with bias (cols tx8..tx8+7, same for all 8 rows)
    unsigned long long acc[8][4];
    {
        float4 q0 = ((const float4*)bias1)[tx * 2];
        float4 q1 = ((const float4*)bias1)[tx * 2 + 1];
        if (MODE == 2) {
            float4 p0 = ((const float4*)bias2)[tx * 2];
            float4 p1 = ((const float4*)bias2)[tx * 2 + 1];
            q0.x += p0.x; q0.y += p0.y; q0.z += p0.z; q0.w += p0.w;
            q1.x += p1.x; q1.y += p1.y; q1.z += p1.z; q1.w += p1.w;
        }
        unsigned long long i0 = pack2(q0.x, q0.y), i1 = pack2(q0.z, q0.w);
        unsigned long long i2 = pack2(q1.x, q1.y), i3 = pack2(q1.z, q1.w);
#pragma unroll
        for (int r = 0; r < 8; r++) { acc[r][0] = i0; acc[r][1] = i1; acc[r][2] = i2; acc[r][3] = i3; }
    }

    float4 a0 = *(const float4*)&Xs[ty8];
    float4 a1 = *(const float4*)&Xs[ty8 + 4];
    ulonglong2 b01 = *(const ulonglong2*)&Ws[tx8];
    ulonglong2 b23 = *(const ulonglong2*)&Ws[tx8 + 4];

#pragma unroll 4
    for (int k = 0; k < 128; ++k) {
        int kn = (k + 1) & 127;
        float4 na0 = *(const float4*)&Xs[kn * 128 + ty8];
        float4 na1 = *(const float4*)&Xs[kn * 128 + ty8 + 4];
        ulonglong2 nb01 = *(const ulonglong2*)&Ws[kn * 128 + tx8];
        ulonglong2 nb23 = *(const ulonglong2*)&Ws[kn * 128 + tx8 + 4];
        float av[8] = {a0.x, a0.y, a0.z, a0.w, a1.x, a1.y, a1.z, a1.w};
#pragma unroll
        for (int r = 0; r < 8; r++) {
            unsigned long long s = splat2(av[r]);
            acc[r][0] = ffma2(s, b01.x, acc[r][0]);
            acc[r][1] = ffma2(s, b01.y, acc[r][1]);
            acc[r][2] = ffma2(s, b23.x, acc[r][2]);
            acc[r][3] = ffma2(s, b23.y, acc[r][3]);
        }
        a0 = na0; a1 = na1; b01 = nb01; b23 = nb23;
    }

    if (MODE == 1) {
        // GATv2 logit epilogue: p = sum_c att[c] * lrelu(xl[c] + xr[dst][c])
        float4 at0 = ((const float4*)att)[tx * 2];
        float4 at1 = ((const float4*)att)[tx * 2 + 1];
#pragma unroll
        for (int r = 0; r < 8; r++) {
            int row = row0 + ty8 + r;
            float p = 0.f;
            if (row < total) {
                int dd = dst_arr[row];
                float4 x0 = ((const float4*)xr)[(size_t)dd * 32 + tx * 2];
                float4 x1 = ((const float4*)xr)[(size_t)dd * 32 + tx * 2 + 1];
                float2 v0 = unpack2(acc[r][0]), v1 = unpack2(acc[r][1]);
                float2 v2 = unpack2(acc[r][2]), v3 = unpack2(acc[r][3]);
                p = at0.x * lrelu(v0.x + x0.x) + at0.y * lrelu(v0.y + x0.y)
                  + at0.z * lrelu(v1.x + x0.z) + at0.w * lrelu(v1.y + x0.w)
                  + at1.x * lrelu(v2.x + x1.x) + at1.y * lrelu(v2.y + x1.y)
                  + at1.z * lrelu(v3.x + x1.z) + at1.w * lrelu(v3.y + x1.w);
            }
#pragma unroll
            for (int o = 8; o; o >>= 1) p += __shfl_xor_sync(0xffffffffu, p, o);
            if (tx == 0 && row < total) logits[row] = p;
        }
    } else {
#pragma unroll
        for (int r = 0; r < 8; r++) {
            int row = row0 + ty8 + r;
            if (row < total) {
                float2 v0 = unpack2(acc[r][0]), v1 = unpack2(acc[r][1]);
                float2 v2 = unpack2(acc[r][2]), v3 = unpack2(acc[r][3]);
                float4 o0 = make_float4(v0.x, v0.y, v1.x, v1.y);
                float4 o1 = make_float4(v2.x, v2.y, v3.x, v3.y);
                if (MODE == 2) {
                    float4 m0 = ((const float4*)addmat)[(size_t)row * 32 + tx * 2];
                    float4 m1 = ((const float4*)addmat)[(size_t)row * 32 + tx * 2 + 1];
                    o0.x += m0.x; o0.y += m0.y; o0.z += m0.z; o0.w += m0.w;
                    o1.x += m1.x; o1.y += m1.y; o1.z += m1.z; o1.w += m1.w;
                }
                ((float4*)Y)[(size_t)row * 32 + tx * 2] = o0;
                ((float4*)Y)[(size_t)row * 32 + tx * 2 + 1] = o1;
            }
        }
    }
}

// ---------------- PP online segment softmax over gathered xl rows ------------
__device__ __forceinline__ float4 seg_softmax_pp(
    const float* __restrict__ xl, const int* __restrict__ srcs,
    int e0, int e1, float4 xrv, float4 attv, int lane) {
    float m = -INFINITY, denom = 0.f;
    float4 acc = make_float4(0.f, 0.f, 0.f, 0.f);

    for (int eb = e0; eb < e1; eb += 4) {
        int g = min(4, e1 - eb);
        int sl = (lane < g) ? srcs[eb + lane] : 0;
        float4 xv[4];
        float lg[4];
#pragma unroll
        for (int i = 0; i < 4; i++) {
            if (i < g) {
                int row = __shfl_sync(0xffffffffu, sl, i);
                xv[i] = ((const float4*)xl)[(size_t)row * 32 + lane];
            }
        }
#pragma unroll
        for (int i = 0; i < 4; i++) {
            if (i < g) {
                float p = lrelu(xv[i].x + xrv.x) * attv.x
                        + lrelu(xv[i].y + xrv.y) * attv.y
                        + lrelu(xv[i].z + xrv.z) * attv.z
                        + lrelu(xv[i].w + xrv.w) * attv.w;
#pragma unroll
                for (int o = 16; o; o >>= 1) p += __shfl_xor_sync(0xffffffffu, p, o);
                lg[i] = p;
            }
        }
        float gm = m;
#pragma unroll
        for (int i = 0; i < 4; i++) if (i < g) gm = fmaxf(gm, lg[i]);
        float sc = __expf(m - gm);
        denom *= sc; acc.x *= sc; acc.y *= sc; acc.z *= sc; acc.w *= sc;
#pragma unroll
        for (int i = 0; i < 4; i++) {
            if (i < g) {
                float w = __expf(lg[i] - gm);
                denom += w;
                acc.x += w * xv[i].x; acc.y += w * xv[i].y;
                acc.z += w * xv[i].z; acc.w += w * xv[i].w;
            }
        }
        m = gm;
    }
    float inv = (denom > 0.f) ? 1.f / denom : 0.f;
    acc.x *= inv; acc.y *= inv; acc.z *= inv; acc.w *= inv;
    return acc;
}

// warp per dst: AP (logit-based softmax over x_aa rows) + PP (online over xl_pp)
__global__ void __launch_bounds__(256) agg_kernel(
    const float* __restrict__ x_aa, const float* __restrict__ logits,
    const int* __restrict__ off_ap, const int* __restrict__ src_ap,
    const float* __restrict__ xl_pp, const float* __restrict__ xr_pp,
    const float* __restrict__ att_pp, const float* __restrict__ bias_pp,
    const int* __restrict__ off_pp, const int* __restrict__ src_pp,
    float* __restrict__ accap, float* __restrict__ pp_out) {
    int t = threadIdx.x, lane = t & 31, warp = t >> 5;
    int dst = blockIdx.x * 8 + warp;

    // ---- AP: softmax weights from precomputed logits, accumulate raw x rows
    int e0 = off_ap[dst], e1 = off_ap[dst + 1];
    float4 acc = make_float4(0.f, 0.f, 0.f, 0.f);
    if (e1 > e0) {
        float m = -INFINITY, denom = 0.f;
        for (int base = e0; base < e1; base += 32) {
            int e = base + lane;
            bool valid = (e < e1);
            float le = valid ? logits[e] : -INFINITY;
            float cm = le;
#pragma unroll
            for (int o = 16; o; o >>= 1) cm = fmaxf(cm, __shfl_xor_sync(0xffffffffu, cm, o));
            if (cm > m) { denom *= __expf(m - cm); m = cm; }
            float w = valid ? __expf(le - m) : 0.f;
#pragma unroll
            for (int o = 16; o; o >>= 1) w += __shfl_xor_sync(0xffffffffu, w, o);
            denom += w;
        }
        float inv = 1.f / denom;
        int e = e0;
        for (; e + 1 < e1; e += 2) {
            int s0 = src_ap[e], s1 = src_ap[e + 1];
            float al0 = __expf(logits[e] - m) * inv;
            float al1 = __expf(logits[e + 1] - m) * inv;
            float4 x0 = ((const float4*)x_aa)[(size_t)s0 * 32 + lane];
            float4 x1 = ((const float4*)x_aa)[(size_t)s1 * 32 + lane];
            acc.x += al0 * x0.x + al1 * x1.x;
            acc.y += al0 * x0.y + al1 * x1.y;
            acc.z += al0 * x0.z + al1 * x1.z;
            acc.w += al0 * x0.w + al1 * x1.w;
        }
        if (e < e1) {
            int s0 = src_ap[e];
            float al0 = __expf(logits[e] - m) * inv;
            float4 x0 = ((const float4*)x_aa)[(size_t)s0 * 32 + lane];
            acc.x += al0 * x0.x; acc.y += al0 * x0.y;
            acc.z += al0 * x0.z; acc.w += al0 * x0.w;
        }
    }
    ((float4*)accap)[(size_t)dst * 32 + lane] = acc;

    // ---- PP: online softmax over precomputed xl_pp rows (L2-resident)
    float4 attv = ((const float4*)att_pp)[lane];
    float4 bsv  = ((const float4*)bias_pp)[lane];
    float4 xrv  = ((const float4*)xr_pp)[(size_t)dst * 32 + lane];
    float4 pp = seg_softmax_pp(xl_pp, src_pp, off_pp[dst], off_pp[dst + 1], xrv, attv, lane);
    pp.x += bsv.x; pp.y += bsv.y; pp.z += bsv.z; pp.w += bsv.w;
    ((float4*)pp_out)[(size_t)dst * 32 + lane] = pp;
}

// ---------------- out = relu(hid) @ W_lin + b_lin  (128 -> 64) ---------------
__global__ void __launch_bounds__(256) final_kernel(
    const float* __restrict__ hid, const float* __restrict__ Wl,
    const float* __restrict__ bl, float* __restrict__ out) {
    extern __shared__ float sm[];
    float* Ws = sm;              // 128*64 = 32KB
    float* hs = sm + D * DOUT;   // 32*128 = 16KB
    int t = threadIdx.x, lane = t & 31, warp = t >> 5;

    for (int i = t; i < D * DOUT / 4; i += 256) ((float4*)Ws)[i] = ((const float4*)Wl)[i];

    int row0 = blockIdx.x * 32 + warp * 4;
#pragma unroll
    for (int r = 0; r < 4; r++) {
        float4 h = ((const float4*)hid)[(size_t)(row0 + r) * 32 + lane];
        h.x = fmaxf(h.x, 0.f); h.y = fmaxf(h.y, 0.f);
        h.z = fmaxf(h.z, 0.f); h.w = fmaxf(h.w, 0.f);
        ((float4*)&hs[(warp * 4 + r) * D])[lane] = h;
    }
    __syncthreads();

    float b0 = bl[lane], b1 = bl[lane + 32];
    float acc0[4], acc1[4];
#pragma unroll
    for (int r = 0; r < 4; r++) { acc0[r] = b0; acc1[r] = b1; }

    for (int k = 0; k < D; k++) {
        float w0 = Ws[k * DOUT + lane];
        float w1 = Ws[k * DOUT + lane + 32];
#pragma unroll
        for (int r = 0; r < 4; r++) {
            float h = hs[(warp * 4 + r) * D + k];
            acc0[r] += h * w0;
            acc1[r] += h * w1;
        }
    }
#pragma unroll
    for (int r = 0; r < 4; r++) {
        int row = row0 + r;
        out[(size_t)row * DOUT + lane] = acc0[r];
        out[(size_t)row * DOUT + lane + 32] = acc1[r];
    }
}

// ---------------- launch ------------------------------------------------------
extern "C" void kernel_launch(void* const* d_in, const int* in_sizes, int n_in,
                              void* d_out, int out_size) {
    const float* x_aa    = (const float*)d_in[0];
    const float* x_prot  = (const float*)d_in[1];
    const int*   ei_ap   = (const int*)d_in[2];
    const int*   ei_pp   = (const int*)d_in[3];
    const float* Wl_ap   = (const float*)d_in[5];
    const float* bl_ap   = (const float*)d_in[6];
    const float* Wr_ap   = (const float*)d_in[7];
    const float* br_ap   = (const float*)d_in[8];
    const float* att_ap  = (const float*)d_in[9];
    const float* bias_ap = (const float*)d_in[10];
    const float* Wl_pp   = (const float*)d_in[11];
    const float* bl_pp   = (const float*)d_in[12];
    const float* Wr_pp   = (const float*)d_in[13];
    const float* br_pp   = (const float*)d_in[14];
    const float* att_pp  = (const float*)d_in[15];
    const float* bias_pp = (const float*)d_in[16];
    const float* W_lin   = (const float*)d_in[17];
    const float* b_lin   = (const float*)d_in[18];
    float* out = (float*)d_out;

    int E_ap = in_sizes[2] / 2;
    int E_pp = in_sizes[3] / 2;

    void* p;
    cudaGetSymbolAddress(&p, g_xl_pp);  float* xl_pp  = (float*)p;
    cudaGetSymbolAddress(&p, g_xr_pp);  float* xr_pp  = (float*)p;
    cudaGetSymbolAddress(&p, g_xr_ap);  float* xr_ap  = (float*)p;
    cudaGetSymbolAddress(&p, g_hid);    float* hid    = (float*)p;
    cudaGetSymbolAddress(&p, g_accap);  float* accap  = (float*)p;
    cudaGetSymbolAddress(&p, g_ppout);  float* ppout  = (float*)p;
    cudaGetSymbolAddress(&p, g_logits); float* logits = (float*)p;
    cudaGetSymbolAddress(&p, g_cnt_ap); int* cnt_ap = (int*)p;
    cudaGetSymbolAddress(&p, g_cnt_pp); int* cnt_pp = (int*)p;
    cudaGetSymbolAddress(&p, g_off_ap); int* off_ap = (int*)p;
    cudaGetSymbolAddress(&p, g_off_pp); int* off_pp = (int*)p;
    cudaGetSymbolAddress(&p, g_cur_ap); int* cur_ap = (int*)p;
    cudaGetSymbolAddress(&p, g_cur_pp); int* cur_pp = (int*)p;
    cudaGetSymbolAddress(&p, g_src_ap); int* src_ap = (int*)p;
    cudaGetSymbolAddress(&p, g_dst_ap); int* dst_ap = (int*)p;
    cudaGetSymbolAddress(&p, g_src_pp); int* src_pp = (int*)p;

    cudaFuncSetAttribute(gemm_kernel<0>, cudaFuncAttributeMaxDynamicSharedMemorySize, 131072);
    cudaFuncSetAttribute(gemm_kernel<1>, cudaFuncAttributeMaxDynamicSharedMemorySize, 131072);
    cudaFuncSetAttribute(gemm_kernel<2>, cudaFuncAttributeMaxDynamicSharedMemorySize, 131072);
    cudaFuncSetAttribute(final_kernel,   cudaFuncAttributeMaxDynamicSharedMemorySize, 49152);

    int E_both = E_ap + E_pp;

    // 0-3: preprocessing (dst-sorted compacted edge lists, dst < BATCH only)
    zero2_kernel<<<(2 * BATCH + 255) / 256, 256>>>(cnt_ap, cnt_pp);
    hist2_kernel<<<(E_both + 255) / 256, 256>>>(ei_ap, E_ap, cnt_ap, ei_pp, E_pp, cnt_pp);
    scan2_kernel<<<2, 1024>>>(cnt_ap, off_ap, cur_ap, cnt_pp, off_pp, cur_pp);
    scatter2_kernel<<<(E_both + 255) / 256, 256>>>(ei_ap, E_ap, cur_ap, src_ap, dst_ap,
                                                   ei_pp, E_pp, cur_pp, src_pp);
    // 4: xr_ap = x_prot @ Wr_ap + br_ap (needed by edge-GEMM logit epilogue)
    gemm_kernel<0><<<BATCH / 128, 256, 131072>>>(
        x_prot, Wr_ap, br_ap, nullptr, xr_ap, BATCH,
        nullptr, nullptr, nullptr, nullptr, nullptr, nullptr, nullptr);
    // 5 (profiled slot): AP edge GEMM -> logits only
    gemm_kernel<1><<<(E_AP_MAX + 127) / 128, 256, 131072>>>(
        x_aa, Wl_ap, bl_ap, nullptr, nullptr, 0,
        src_ap, &off_ap[BATCH], dst_ap, xr_ap, att_ap, logits, nullptr);
    // 6,7: PP node transforms
    gemm_kernel<0><<<(N_PROT_C + 127) / 128, 256, 131072>>>(
        x_prot, Wl_pp, bl_pp, nullptr, xl_pp, N_PROT_C,
        nullptr, nullptr, nullptr, nullptr, nullptr, nullptr, nullptr);
    gemm_kernel<0><<<BATCH / 128, 256, 131072>>>(
        x_prot, Wr_pp, br_pp, nullptr, xr_pp, BATCH,
        nullptr, nullptr, nullptr, nullptr, nullptr, nullptr, nullptr);
    // 8: fused AP (logit softmax over x_aa) + PP (online over xl_pp) aggregation
    agg_kernel<<<BATCH / 8, 256>>>(x_aa, logits, off_ap, src_ap,
                                   xl_pp, xr_pp, att_pp, bias_pp, off_pp, src_pp,
                                   accap, ppout);
    // 9: hid = accap @ Wl_ap + bl_ap + bias_ap + ppout
    gemm_kernel<2><<<BATCH / 128, 256, 131072>>>(
        accap, Wl_ap, bl_ap, bias_ap, hid, BATCH,
        nullptr, nullptr, nullptr, nullptr, nullptr, nullptr, ppout);
    // 10: relu + final linear
    final_kernel<<<BATCH / 32, 256, 49152>>>(hid, W_lin, b_lin, out);
}

// round 4
// speedup vs baseline: 1.2222x; 1.2222x over previous
#include <cuda_runtime.h>
#include <math.h>

#define N_AA_C   300000
#define N_PROT_C 30000
#define D        128
#define DOUT     64
#define E_AP_MAX 300000
#define E_PP_MAX 960000
#define BATCH    16384
#define NEG      0.2f

// ---------------- device scratch (static; no runtime allocation) -------------
__device__ float g_xl_pp[N_PROT_C * D];   // 15.4 MB (L2-resident)
__device__ float g_xr_pp[BATCH * D];
__device__ float g_xr_ap[BATCH * D];
__device__ float g_hid[BATCH * D];
__device__ float g_accap[BATCH * D];      // AP aggregated x (input space)
__device__ float g_ppout[BATCH * D];      // PP branch output
__device__ float g_logits[E_AP_MAX];

__device__ int g_cnt_ap[BATCH];
__device__ int g_cnt_pp[BATCH];
__device__ int g_off_ap[BATCH + 1];
__device__ int g_off_pp[BATCH + 1];
__device__ int g_cur_ap[BATCH];
__device__ int g_cur_pp[BATCH];
__device__ int g_src_ap[E_AP_MAX];
__device__ int g_dst_ap[E_AP_MAX];
__device__ int g_src_pp[E_PP_MAX];

__device__ __forceinline__ float lrelu(float x) { return x > 0.f ? x : NEG * x; }

// packed f32x2 helpers (Blackwell FFMA2 — only reachable via PTX)
__device__ __forceinline__ unsigned long long splat2(float x) {
    unsigned long long d;
    asm("mov.b64 %0, {%1, %1};" : "=l"(d) : "r"(__float_as_uint(x)));
    return d;
}
__device__ __forceinline__ unsigned long long pack2(float lo, float hi) {
    unsigned long long d;
    asm("mov.b64 %0, {%1, %2};" : "=l"(d) : "r"(__float_as_uint(lo)), "r"(__float_as_uint(hi)));
    return d;
}
__device__ __forceinline__ float2 unpack2(unsigned long long u) {
    float2 f;
    asm("mov.b64 {%0, %1}, %2;" : "=f"(f.x), "=f"(f.y) : "l"(u));
    return f;
}
__device__ __forceinline__ unsigned long long ffma2(
    unsigned long long a, unsigned long long b, unsigned long long c) {
    unsigned long long d;
    asm("fma.rn.f32x2 %0, %1, %2, %3;" : "=l"(d) : "l"(a), "l"(b), "l"(c));
    return d;
}

// ---------------- fused preprocessing kernels --------------------------------
__global__ void zero2_kernel(int* a, int* b) {
    int i = blockIdx.x * blockDim.x + threadIdx.x;
    if (i < BATCH) a[i] = 0;
    else if (i < 2 * BATCH) b[i - BATCH] = 0;
}

__global__ void hist2_kernel(const int* __restrict__ ei_ap, int E_ap, int* __restrict__ cnt_ap,
                             const int* __restrict__ ei_pp, int E_pp, int* __restrict__ cnt_pp) {
    int i = blockIdx.x * blockDim.x + threadIdx.x;
    if (i < E_ap) {
        int d = ei_ap[E_ap + i];
        if (d < BATCH) atomicAdd(&cnt_ap[d], 1);
    } else if (i < E_ap + E_pp) {
        int j = i - E_ap;
        int d = ei_pp[E_pp + j];
        if (d < BATCH) atomicAdd(&cnt_pp[d], 1);
    }
}

__global__ void scan2_kernel(const int* __restrict__ cnt_ap, int* __restrict__ off_ap, int* __restrict__ cur_ap,
                             const int* __restrict__ cnt_pp, int* __restrict__ off_pp, int* __restrict__ cur_pp) {
    const int* cnt = blockIdx.x ? cnt_pp : cnt_ap;
    int* off = blockIdx.x ? off_pp : off_ap;
    int* cur = blockIdx.x ? cur_pp : cur_ap;
    __shared__ int s[1024];
    int t = threadIdx.x;
    int v[16];
    int run = 0;
#pragma unroll
    for (int i = 0; i < 16; i++) { v[i] = run; run += cnt[t * 16 + i]; }
    s[t] = run;
    __syncthreads();
    for (int d = 1; d < 1024; d <<= 1) {
        int add = (t >= d) ? s[t - d] : 0;
        __syncthreads();
        s[t] += add;
        __syncthreads();
    }
    int base = (t > 0) ? s[t - 1] : 0;
#pragma unroll
    for (int i = 0; i < 16; i++) {
        int o = base + v[i];
        off[t * 16 + i] = o;
        cur[t * 16 + i] = o;
    }
    if (t == 1023) off[16384] = s[1023];
}

__global__ void scatter2_kernel(const int* __restrict__ ei_ap, int E_ap, int* __restrict__ cur_ap,
                                int* __restrict__ src_ap, int* __restrict__ dst_ap,
                                const int* __restrict__ ei_pp, int E_pp, int* __restrict__ cur_pp,
                                int* __restrict__ src_pp) {
    int i = blockIdx.x * blockDim.x + threadIdx.x;
    if (i < E_ap) {
        int d = ei_ap[E_ap + i];
        if (d < BATCH) {
            int p = atomicAdd(&cur_ap[d], 1);
            src_ap[p] = ei_ap[i];
            dst_ap[p] = d;
        }
    } else if (i < E_ap + E_pp) {
        int j = i - E_ap;
        int d = ei_pp[E_pp + j];
        if (d < BATCH) {
            int p = atomicAdd(&cur_pp[d], 1);
            src_pp[p] = ei_pp[j];
        }
    }
}

// ---------------- 128x128-tile GEMM, k-chunked double-buffered ---------------
// 256 thr, 8x8 per-thread register block, K in 8 chunks of 16, 32 KB smem.
// MODE 0: Y = X @ W + bias1
// MODE 1: gather rows via srcs; per-row GATv2 logits only
// MODE 2: Y = X @ W + bias1 + bias2 + addmat
template <int MODE>
__global__ void __launch_bounds__(256) gemm_kernel(
    const float* __restrict__ X, const float* __restrict__ W,
    const float* __restrict__ bias1, const float* __restrict__ bias2,
    float* __restrict__ Y, int nrows_const,
    const int* __restrict__ srcs, const int* __restrict__ total_ptr,
    const int* __restrict__ dst_arr, const float* __restrict__ xr,
    const float* __restrict__ att, float* __restrict__ logits,
    const float* __restrict__ addmat) {
    int total = (MODE == 1) ? *total_ptr : nrows_const;
    int row0 = blockIdx.x * 128;
    if (row0 >= total) return;

    __shared__ float Ws[2][16][128];   // [buf][k-in-chunk][n]
    __shared__ float Xs[2][16][128];   // [buf][k-in-chunk][m] (transposed)

    int t = threadIdx.x;
    int tx = t & 15, ty = t >> 4;
    int tx8 = tx * 8, ty8 = ty * 8;

    // staging assignments
    int m_a = t >> 2, kq = t & 3;      // X: thread loads rows m_a and m_a+64, float4 col kq
    int m_b = m_a + 64;
    int kw_a = t >> 5, nw = t & 31;    // W: rows kw_a and kw_a+8 (in chunk), float4 col nw
    int kw_b = kw_a + 8;

    int ra = row0 + m_a, rb = row0 + m_b;
    int rra = (ra < total) ? ((MODE == 1) ? srcs[ra] : ra) : 0;
    int rrb = (rb < total) ? ((MODE == 1) ? srcs[rb] : rb) : 0;
    const float4* X4 = (const float4*)X;
    const float4* W4 = (const float4*)W;

    // accumulator init with bias (cols tx8..tx8+7)
    unsigned long long acc[8][4];
    {
        float4 q0 = ((const float4*)bias1)[tx * 2];
        float4 q1 = ((const float4*)bias1)[tx * 2 + 1];
        if (MODE == 2) {
            float4 p0 = ((const float4*)bias2)[tx * 2];
            float4 p1 = ((const float4*)bias2)[tx * 2 + 1];
            q0.x += p0.x; q0.y += p0.y; q0.z += p0.z; q0.w += p0.w;
            q1.x += p1.x; q1.y += p1.y; q1.z += p1.z; q1.w += p1.w;
        }
        unsigned long long i0 = pack2(q0.x, q0.y), i1 = pack2(q0.z, q0.w);
        unsigned long long i2 = pack2(q1.x, q1.y), i3 = pack2(q1.z, q1.w);
#pragma unroll
        for (int r = 0; r < 8; r++) { acc[r][0] = i0; acc[r][1] = i1; acc[r][2] = i2; acc[r][3] = i3; }
    }

    // prologue: stage chunk 0
    float4 xg_a = X4[(size_t)rra * 32 + kq];
    float4 xg_b = X4[(size_t)rrb * 32 + kq];
    float4 wg_a = W4[kw_a * 32 + nw];
    float4 wg_b = W4[kw_b * 32 + nw];
    {
        ((float4*)&Ws[0][kw_a][nw * 4])[0] = wg_a;
        ((float4*)&Ws[0][kw_b][nw * 4])[0] = wg_b;
        Xs[0][kq * 4 + 0][m_a] = xg_a.x; Xs[0][kq * 4 + 1][m_a] = xg_a.y;
        Xs[0][kq * 4 + 2][m_a] = xg_a.z; Xs[0][kq * 4 + 3][m_a] = xg_a.w;
        Xs[0][kq * 4 + 0][m_b] = xg_b.x; Xs[0][kq * 4 + 1][m_b] = xg_b.y;
        Xs[0][kq * 4 + 2][m_b] = xg_b.z; Xs[0][kq * 4 + 3][m_b] = xg_b.w;
    }
    __syncthreads();

#pragma unroll
    for (int c = 0; c < 8; c++) {
        int buf = c & 1;
        if (c < 7) {
            xg_a = X4[(size_t)rra * 32 + (c + 1) * 4 + kq];
            xg_b = X4[(size_t)rrb * 32 + (c + 1) * 4 + kq];
            wg_a = W4[((c + 1) * 16 + kw_a) * 32 + nw];
            wg_b = W4[((c + 1) * 16 + kw_b) * 32 + nw];
        }
#pragma unroll
        for (int kk = 0; kk < 16; kk++) {
            float4 a0 = *(const float4*)&Xs[buf][kk][ty8];
            float4 a1 = *(const float4*)&Xs[buf][kk][ty8 + 4];
            ulonglong2 b01 = *(const ulonglong2*)&Ws[buf][kk][tx8];
            ulonglong2 b23 = *(const ulonglong2*)&Ws[buf][kk][tx8 + 4];
            float av[8] = {a0.x, a0.y, a0.z, a0.w, a1.x, a1.y, a1.z, a1.w};
#pragma unroll
            for (int r = 0; r < 8; r++) {
                unsigned long long s = splat2(av[r]);
                acc[r][0] = ffma2(s, b01.x, acc[r][0]);
                acc[r][1] = ffma2(s, b01.y, acc[r][1]);
                acc[r][2] = ffma2(s, b23.x, acc[r][2]);
                acc[r][3] = ffma2(s, b23.y, acc[r][3]);
            }
        }
        if (c < 7) {
            int nb = buf ^ 1;
            ((float4*)&Ws[nb][kw_a][nw * 4])[0] = wg_a;
            ((float4*)&Ws[nb][kw_b][nw * 4])[0] = wg_b;
            Xs[nb][kq * 4 + 0][m_a] = xg_a.x; Xs[nb][kq * 4 + 1][m_a] = xg_a.y;
            Xs[nb][kq * 4 + 2][m_a] = xg_a.z; Xs[nb][kq * 4 + 3][m_a] = xg_a.w;
            Xs[nb][kq * 4 + 0][m_b] = xg_b.x; Xs[nb][kq * 4 + 1][m_b] = xg_b.y;
            Xs[nb][kq * 4 + 2][m_b] = xg_b.z; Xs[nb][kq * 4 + 3][m_b] = xg_b.w;
            __syncthreads();
        }
    }

    if (MODE == 1) {
        // GATv2 logit epilogue: p = sum_c att[c] * lrelu(xl[c] + xr[dst][c])
        float4 at0 = ((const float4*)att)[tx * 2];
        float4 at1 = ((const float4*)att)[tx * 2 + 1];
#pragma unroll
        for (int r = 0; r < 8; r++) {
            int row = row0 + ty8 + r;
            float p = 0.f;
            if (row < total) {
                int dd = dst_arr[row];
                float4 x0 = ((const float4*)xr)[(size_t)dd * 32 + tx * 2];
                float4 x1 = ((const float4*)xr)[(size_t)dd * 32 + tx * 2 + 1];
                float2 v0 = unpack2(acc[r][0]), v1 = unpack2(acc[r][1]);
                float2 v2 = unpack2(acc[r][2]), v3 = unpack2(acc[r][3]);
                p = at0.x * lrelu(v0.x + x0.x) + at0.y * lrelu(v0.y + x0.y)
                  + at0.z * lrelu(v1.x + x0.z) + at0.w * lrelu(v1.y + x0.w)
                  + at1.x * lrelu(v2.x + x1.x) + at1.y * lrelu(v2.y + x1.y)
                  + at1.z * lrelu(v3.x + x1.z) + at1.w * lrelu(v3.y + x1.w);
            }
#pragma unroll
            for (int o = 8; o; o >>= 1) p += __shfl_xor_sync(0xffffffffu, p, o);
            if (tx == 0 && row < total) logits[row] = p;
        }
    } else {
#pragma unroll
        for (int r = 0; r < 8; r++) {
            int row = row0 + ty8 + r;
            if (row < total) {
                float2 v0 = unpack2(acc[r][0]), v1 = unpack2(acc[r][1]);
                float2 v2 = unpack2(acc[r][2]), v3 = unpack2(acc[r][3]);
                float4 o0 = make_float4(v0.x, v0.y, v1.x, v1.y);
                float4 o1 = make_float4(v2.x, v2.y, v3.x, v3.y);
                if (MODE == 2) {
                    float4 m0 = ((const float4*)addmat)[(size_t)row * 32 + tx * 2];
                    float4 m1 = ((const float4*)addmat)[(size_t)row * 32 + tx * 2 + 1];
                    o0.x += m0.x; o0.y += m0.y; o0.z += m0.z; o0.w += m0.w;
                    o1.x += m1.x; o1.y += m1.y; o1.z += m1.z; o1.w += m1.w;
                }
                ((float4*)Y)[(size_t)row * 32 + tx * 2] = o0;
                ((float4*)Y)[(size_t)row * 32 + tx * 2 + 1] = o1;
            }
        }
    }
}

// ---------------- PP online segment softmax over gathered xl rows ------------
__device__ __forceinline__ float4 seg_softmax_pp(
    const float* __restrict__ xl, const int* __restrict__ srcs,
    int e0, int e1, float4 xrv, float4 attv, int lane) {
    float m = -INFINITY, denom = 0.f;
    float4 acc = make_float4(0.f, 0.f, 0.f, 0.f);

    for (int eb = e0; eb < e1; eb += 4) {
        int g = min(4, e1 - eb);
        int sl = (lane < g) ? srcs[eb + lane] : 0;
        float4 xv[4];
        float lg[4];
#pragma unroll
        for (int i = 0; i < 4; i++) {
            if (i < g) {
                int row = __shfl_sync(0xffffffffu, sl, i);
                xv[i] = ((const float4*)xl)[(size_t)row * 32 + lane];
            }
        }
#pragma unroll
        for (int i = 0; i < 4; i++) {
            if (i < g) {
                float p = lrelu(xv[i].x + xrv.x) * attv.x
                        + lrelu(xv[i].y + xrv.y) * attv.y
                        + lrelu(xv[i].z + xrv.z) * attv.z
                        + lrelu(xv[i].w + xrv.w) * attv.w;
#pragma unroll
                for (int o = 16; o; o >>= 1) p += __shfl_xor_sync(0xffffffffu, p, o);
                lg[i] = p;
            }
        }
        float gm = m;
#pragma unroll
        for (int i = 0; i < 4; i++) if (i < g) gm = fmaxf(gm, lg[i]);
        float sc = __expf(m - gm);
        denom *= sc; acc.x *= sc; acc.y *= sc; acc.z *= sc; acc.w *= sc;
#pragma unroll
        for (int i = 0; i < 4; i++) {
            if (i < g) {
                float w = __expf(lg[i] - gm);
                denom += w;
                acc.x += w * xv[i].x; acc.y += w * xv[i].y;
                acc.z += w * xv[i].z; acc.w += w * xv[i].w;
            }
        }
        m = gm;
    }
    float inv = (denom > 0.f) ? 1.f / denom : 0.f;
    acc.x *= inv; acc.y *= inv; acc.z *= inv; acc.w *= inv;
    return acc;
}

// warp per dst: AP (logit-based softmax over x_aa rows) + PP (online over xl_pp)
__global__ void __launch_bounds__(256) agg_kernel(
    const float* __restrict__ x_aa, const float* __restrict__ logits,
    const int* __restrict__ off_ap, const int* __restrict__ src_ap,
    const float* __restrict__ xl_pp, const float* __restrict__ xr_pp,
    const float* __restrict__ att_pp, const float* __restrict__ bias_pp,
    const int* __restrict__ off_pp, const int* __restrict__ src_pp,
    float* __restrict__ accap, float* __restrict__ pp_out) {
    int t = threadIdx.x, lane = t & 31, warp = t >> 5;
    int dst = blockIdx.x * 8 + warp;

    // ---- AP: softmax weights from precomputed logits, accumulate raw x rows
    int e0 = off_ap[dst], e1 = off_ap[dst + 1];
    float4 acc = make_float4(0.f, 0.f, 0.f, 0.f);
    if (e1 > e0) {
        float m = -INFINITY, denom = 0.f;
        for (int base = e0; base < e1; base += 32) {
            int e = base + lane;
            bool valid = (e < e1);
            float le = valid ? logits[e] : -INFINITY;
            float cm = le;
#pragma unroll
            for (int o = 16; o; o >>= 1) cm = fmaxf(cm, __shfl_xor_sync(0xffffffffu, cm, o));
            if (cm > m) { denom *= __expf(m - cm); m = cm; }
            float w = valid ? __expf(le - m) : 0.f;
#pragma unroll
            for (int o = 16; o; o >>= 1) w += __shfl_xor_sync(0xffffffffu, w, o);
            denom += w;
        }
        float inv = 1.f / denom;
        int e = e0;
        for (; e + 3 < e1; e += 4) {
            int s0 = src_ap[e], s1 = src_ap[e + 1], s2 = src_ap[e + 2], s3 = src_ap[e + 3];
            float4 x0 = ((const float4*)x_aa)[(size_t)s0 * 32 + lane];
            float4 x1 = ((const float4*)x_aa)[(size_t)s1 * 32 + lane];
            float4 x2 = ((const float4*)x_aa)[(size_t)s2 * 32 + lane];
            float4 x3 = ((const float4*)x_aa)[(size_t)s3 * 32 + lane];
            float al0 = __expf(logits[e] - m) * inv;
            float al1 = __expf(logits[e + 1] - m) * inv;
            float al2 = __expf(logits[e + 2] - m) * inv;
            float al3 = __expf(logits[e + 3] - m) * inv;
            acc.x += al0 * x0.x + al1 * x1.x + al2 * x2.x + al3 * x3.x;
            acc.y += al0 * x0.y + al1 * x1.y + al2 * x2.y + al3 * x3.y;
            acc.z += al0 * x0.z + al1 * x1.z + al2 * x2.z + al3 * x3.z;
            acc.w += al0 * x0.w + al1 * x1.w + al2 * x2.w + al3 * x3.w;
        }
        for (; e < e1; e++) {
            int s0 = src_ap[e];
            float al0 = __expf(logits[e] - m) * inv;
            float4 x0 = ((const float4*)x_aa)[(size_t)s0 * 32 + lane];
            acc.x += al0 * x0.x; acc.y += al0 * x0.y;
            acc.z += al0 * x0.z; acc.w += al0 * x0.w;
        }
    }
    ((float4*)accap)[(size_t)dst * 32 + lane] = acc;

    // ---- PP: online softmax over precomputed xl_pp rows (L2-resident)
    float4 attv = ((const float4*)att_pp)[lane];
    float4 bsv  = ((const float4*)bias_pp)[lane];
    float4 xrv  = ((const float4*)xr_pp)[(size_t)dst * 32 + lane];
    float4 pp = seg_softmax_pp(xl_pp, src_pp, off_pp[dst], off_pp[dst + 1], xrv, attv, lane);
    pp.x += bsv.x; pp.y += bsv.y; pp.z += bsv.z; pp.w += bsv.w;
    ((float4*)pp_out)[(size_t)dst * 32 + lane] = pp;
}

// ---------------- out = relu(hid) @ W_lin + b_lin  (128 -> 64) ---------------
__global__ void __launch_bounds__(256) final_kernel(
    const float* __restrict__ hid, const float* __restrict__ Wl,
    const float* __restrict__ bl, float* __restrict__ out) {
    extern __shared__ float sm[];
    float* Ws = sm;              // 128*64 = 32KB
    float* hs = sm + D * DOUT;   // 32*128 = 16KB
    int t = threadIdx.x, lane = t & 31, warp = t >> 5;

    for (int i = t; i < D * DOUT / 4; i += 256) ((float4*)Ws)[i] = ((const float4*)Wl)[i];

    int row0 = blockIdx.x * 32 + warp * 4;
#pragma unroll
    for (int r = 0; r < 4; r++) {
        float4 h = ((const float4*)hid)[(size_t)(row0 + r) * 32 + lane];
        h.x = fmaxf(h.x, 0.f); h.y = fmaxf(h.y, 0.f);
        h.z = fmaxf(h.z, 0.f); h.w = fmaxf(h.w, 0.f);
        ((float4*)&hs[(warp * 4 + r) * D])[lane] = h;
    }
    __syncthreads();

    float b0 = bl[lane], b1 = bl[lane + 32];
    float acc0[4], acc1[4];
#pragma unroll
    for (int r = 0; r < 4; r++) { acc0[r] = b0; acc1[r] = b1; }

    for (int k = 0; k < D; k++) {
        float w0 = Ws[k * DOUT + lane];
        float w1 = Ws[k * DOUT + lane + 32];
#pragma unroll
        for (int r = 0; r < 4; r++) {
            float h = hs[(warp * 4 + r) * D + k];
            acc0[r] += h * w0;
            acc1[r] += h * w1;
        }
    }
#pragma unroll
    for (int r = 0; r < 4; r++) {
        int row = row0 + r;
        out[(size_t)row * DOUT + lane] = acc0[r];
        out[(size_t)row * DOUT + lane + 32] = acc1[r];
    }
}

// ---------------- launch ------------------------------------------------------
extern "C" void kernel_launch(void* const* d_in, const int* in_sizes, int n_in,
                              void* d_out, int out_size) {
    const float* x_aa    = (const float*)d_in[0];
    const float* x_prot  = (const float*)d_in[1];
    const int*   ei_ap   = (const int*)d_in[2];
    const int*   ei_pp   = (const int*)d_in[3];
    const float* Wl_ap   = (const float*)d_in[5];
    const float* bl_ap   = (const float*)d_in[6];
    const float* Wr_ap   = (const float*)d_in[7];
    const float* br_ap   = (const float*)d_in[8];
    const float* att_ap  = (const float*)d_in[9];
    const float* bias_ap = (const float*)d_in[10];
    const float* Wl_pp   = (const float*)d_in[11];
    const float* bl_pp   = (const float*)d_in[12];
    const float* Wr_pp   = (const float*)d_in[13];
    const float* br_pp   = (const float*)d_in[14];
    const float* att_pp  = (const float*)d_in[15];
    const float* bias_pp = (const float*)d_in[16];
    const float* W_lin   = (const float*)d_in[17];
    const float* b_lin   = (const float*)d_in[18];
    float* out = (float*)d_out;

    int E_ap = in_sizes[2] / 2;
    int E_pp = in_sizes[3] / 2;

    void* p;
    cudaGetSymbolAddress(&p, g_xl_pp);  float* xl_pp  = (float*)p;
    cudaGetSymbolAddress(&p, g_xr_pp);  float* xr_pp  = (float*)p;
    cudaGetSymbolAddress(&p, g_xr_ap);  float* xr_ap  = (float*)p;
    cudaGetSymbolAddress(&p, g_hid);    float* hid    = (float*)p;
    cudaGetSymbolAddress(&p, g_accap);  float* accap  = (float*)p;
    cudaGetSymbolAddress(&p, g_ppout);  float* ppout  = (float*)p;
    cudaGetSymbolAddress(&p, g_logits); float* logits = (float*)p;
    cudaGetSymbolAddress(&p, g_cnt_ap); int* cnt_ap = (int*)p;
    cudaGetSymbolAddress(&p, g_cnt_pp); int* cnt_pp = (int*)p;
    cudaGetSymbolAddress(&p, g_off_ap); int* off_ap = (int*)p;
    cudaGetSymbolAddress(&p, g_off_pp); int* off_pp = (int*)p;
    cudaGetSymbolAddress(&p, g_cur_ap); int* cur_ap = (int*)p;
    cudaGetSymbolAddress(&p, g_cur_pp); int* cur_pp = (int*)p;
    cudaGetSymbolAddress(&p, g_src_ap); int* src_ap = (int*)p;
    cudaGetSymbolAddress(&p, g_dst_ap); int* dst_ap = (int*)p;
    cudaGetSymbolAddress(&p, g_src_pp); int* src_pp = (int*)p;

    cudaFuncSetAttribute(final_kernel, cudaFuncAttributeMaxDynamicSharedMemorySize, 49152);

    int E_both = E_ap + E_pp;

    // 0-2: preprocessing front half
    zero2_kernel<<<(2 * BATCH + 255) / 256, 256>>>(cnt_ap, cnt_pp);
    hist2_kernel<<<(E_both + 255) / 256, 256>>>(ei_ap, E_ap, cnt_ap, ei_pp, E_pp, cnt_pp);
    scan2_kernel<<<2, 1024>>>(cnt_ap, off_ap, cur_ap, cnt_pp, off_pp, cur_pp);
    // 3 (ncu slot): xl_pp = x_prot @ Wl_pp + bl_pp — A/B vs round 2's 42.4us
    gemm_kernel<0><<<(N_PROT_C + 127) / 128, 256>>>(
        x_prot, Wl_pp, bl_pp, nullptr, xl_pp, N_PROT_C,
        nullptr, nullptr, nullptr, nullptr, nullptr, nullptr, nullptr);
    // 4: scatter src indices into dst-sorted order
    scatter2_kernel<<<(E_both + 255) / 256, 256>>>(ei_ap, E_ap, cur_ap, src_ap, dst_ap,
                                                   ei_pp, E_pp, cur_pp, src_pp);
    // 5: xr_ap = x_prot @ Wr_ap + br_ap (needed by edge-GEMM logit epilogue)
    gemm_kernel<0><<<BATCH / 128, 256>>>(
        x_prot, Wr_ap, br_ap, nullptr, xr_ap, BATCH,
        nullptr, nullptr, nullptr, nullptr, nullptr, nullptr, nullptr);
    // 6: AP edge GEMM -> logits only
    gemm_kernel<1><<<(E_AP_MAX + 127) / 128, 256>>>(
        x_aa, Wl_ap, bl_ap, nullptr, nullptr, 0,
        src_ap, &off_ap[BATCH], dst_ap, xr_ap, att_ap, logits, nullptr);
    // 7: xr_pp
    gemm_kernel<0><<<BATCH / 128, 256>>>(
        x_prot, Wr_pp, br_pp, nullptr, xr_pp, BATCH,
        nullptr, nullptr, nullptr, nullptr, nullptr, nullptr, nullptr);
    // 8: fused AP (logit softmax over x_aa) + PP (online over xl_pp) aggregation
    agg_kernel<<<BATCH / 8, 256>>>(x_aa, logits, off_ap, src_ap,
                                   xl_pp, xr_pp, att_pp, bias_pp, off_pp, src_pp,
                                   accap, ppout);
    // 9: hid = accap @ Wl_ap + bl_ap + bias_ap + ppout
    gemm_kernel<2><<<BATCH / 128, 256>>>(
        accap, Wl_ap, bl_ap, bias_ap, hid, BATCH,
        nullptr, nullptr, nullptr, nullptr, nullptr, nullptr, ppout);
    // 10: relu + final linear
    final_kernel<<<BATCH / 32, 256, 49152>>>(hid, W_lin, b_lin, out);
}